// round 4
// baseline (speedup 1.0000x reference)
#include <cuda_runtime.h>
#include <cuda_fp16.h>

#define N_NODES 100000
#define N_EDGES 6400000
#define E_TOT   (N_EDGES + N_NODES)
#define HID 64

// ---------------- scratch (static device globals; no allocation) ----------------
__device__ __half g_bufA[N_NODES * HID];  // ping  (packed: half2 at n*32+l = feats 2l,2l+1)
__device__ __half g_bufB[N_NODES * HID];  // pong
__device__ float g_s[N_NODES];            // h @ a_s (fp32)
__device__ float g_d[N_NODES];            // h @ a_d (fp32)
__device__ int   g_csr[E_TOT];            // src ids, grouped by dst
__device__ int   g_rowptr[N_NODES + 1];
__device__ int   g_cnt[N_NODES];
__device__ int   g_cursor[N_NODES];
__device__ float2 g_pL[N_NODES];          // last layer: (hL, sL) packed
__device__ float g_dL[N_NODES];

// ---------------- CSR build ----------------
__global__ void k_zero_cnt() {
    int i = blockIdx.x * blockDim.x + threadIdx.x;
    if (i < N_NODES) g_cnt[i] = 0;
}

// edge_index is int32 on device (JAX x64 disabled)
__global__ void k_hist(const int* __restrict__ ei) {
    int i = blockIdx.x * blockDim.x + threadIdx.x;
    if (i >= E_TOT) return;
    int dst = (i < N_EDGES) ? ei[N_EDGES + i] : (i - N_EDGES);  // self-loops appended
    atomicAdd(&g_cnt[dst], 1);
}

// single-block exclusive scan over 100k counts -> rowptr (+ cursor copy)
__global__ void k_scan() {
    __shared__ int sh[32];
    int tid = threadIdx.x, lane = tid & 31, wid = tid >> 5;
    int carry = 0;
    if (tid == 0) g_rowptr[0] = 0;
    for (int base = 0; base < N_NODES; base += 1024) {
        int i = base + tid;
        int v = (i < N_NODES) ? g_cnt[i] : 0;
        int x = v;
        #pragma unroll
        for (int o = 1; o < 32; o <<= 1) {
            int y = __shfl_up_sync(0xffffffffu, x, o);
            if (lane >= o) x += y;
        }
        if (lane == 31) sh[wid] = x;
        __syncthreads();
        if (wid == 0) {
            int y = sh[lane];
            #pragma unroll
            for (int o = 1; o < 32; o <<= 1) {
                int z = __shfl_up_sync(0xffffffffu, y, o);
                if (lane >= o) y += z;
            }
            sh[lane] = y;
        }
        __syncthreads();
        int off = (wid > 0) ? sh[wid - 1] : 0;
        int incl = x + off + carry;
        if (i < N_NODES) { g_rowptr[i + 1] = incl; g_cursor[i] = incl - v; }
        carry += sh[31];
        __syncthreads();
    }
}

__global__ void k_scatter(const int* __restrict__ ei) {
    int i = blockIdx.x * blockDim.x + threadIdx.x;
    if (i >= E_TOT) return;
    int src, dst;
    if (i < N_EDGES) { src = ei[i]; dst = ei[N_EDGES + i]; }
    else             { src = i - N_EDGES; dst = src; }
    int pos = atomicAdd(&g_cursor[dst], 1);
    g_csr[pos] = src;
}

// ---------------- layer 0: h = x (Nx1) * W0 (1x64); s,d scalars ----------------
__global__ void k_layer0(const float* __restrict__ x, const float* __restrict__ W0,
                         const float* __restrict__ as0, const float* __restrict__ ad0) {
    int idx = blockIdx.x * blockDim.x + threadIdx.x;
    if (idx >= N_NODES * HID) return;
    int n = idx >> 6, c = idx & 63;
    float xv = x[n];
    g_bufB[idx] = __float2half(xv * W0[c]);
    if (c == 0) {
        float c1 = 0.f, c2 = 0.f;
        #pragma unroll
        for (int k = 0; k < HID; k++) { c1 += W0[k] * as0[k]; c2 += W0[k] * ad0[k]; }
        g_s[n] = xv * c1;
        g_d[n] = xv * c2;
    }
}

// ---------------- 64x64 GEMM + attention projections (warp per node) ----------------
// Packed layout: half2 at row*32+lane holds features (2l, 2l+1).
__global__ void __launch_bounds__(256)
k_gemm64(const __half2* __restrict__ hin2, const float* __restrict__ W,
         const float* __restrict__ a_s, const float* __restrict__ a_d,
         __half2* __restrict__ hout2) {
    __shared__ float Wsm[HID * HID];
    int tid = threadIdx.x;
    for (int i = tid; i < HID * HID; i += 256) Wsm[i] = W[i];
    __syncthreads();
    const float2* W2 = (const float2*)Wsm;   // row k: W2[k*32+l] = (W[k,2l], W[k,2l+1])
    int lane = tid & 31, warp = tid >> 5;
    float2 as2 = ((const float2*)a_s)[lane];  // (a_s[2l], a_s[2l+1])
    float2 ad2 = ((const float2*)a_d)[lane];
    int nbase = blockIdx.x * 64 + warp * 8;
    for (int j = 0; j < 8; j++) {
        int n = nbase + j;
        if (n >= N_NODES) return;
        float2 f = __half22float2(hin2[n * 32 + lane]);  // feats (2l, 2l+1)
        float accx = 0.f, accy = 0.f;
        #pragma unroll
        for (int kk = 0; kk < 32; kk++) {
            float bx = __shfl_sync(0xffffffffu, f.x, kk);   // feature 2kk
            float by = __shfl_sync(0xffffffffu, f.y, kk);   // feature 2kk+1
            float2 w0 = W2[(2 * kk) * 32 + lane];
            float2 w1 = W2[(2 * kk + 1) * 32 + lane];
            accx += bx * w0.x + by * w1.x;
            accy += bx * w0.y + by * w1.y;
        }
        hout2[n * 32 + lane] = __floats2half2_rn(accx, accy);
        float ps = accx * as2.x + accy * as2.y;
        float pd = accx * ad2.x + accy * ad2.y;
        #pragma unroll
        for (int o = 16; o > 0; o >>= 1) {
            ps += __shfl_down_sync(0xffffffffu, ps, o);
            pd += __shfl_down_sync(0xffffffffu, pd, o);
        }
        if (lane == 0) { g_s[n] = ps; g_d[n] = pd; }
    }
}

// ---------------- 64-wide attention aggregation: warp per dst node ----------------
// Single pass (softmax shift-invariance; logits O(1), exp cannot overflow).
// One 128B line per edge gather (fp16 row). fp32 accumulation.
__global__ void __launch_bounds__(256)
k_agg64(const __half2* __restrict__ h2, const float2* __restrict__ bias2,
        __half2* __restrict__ out2) {
    int gtid = blockIdx.x * blockDim.x + threadIdx.x;
    int node = gtid >> 5, lane = gtid & 31;
    if (node >= N_NODES) return;
    int r0 = g_rowptr[node], r1 = g_rowptr[node + 1];
    float dn = g_d[node];

    float acc0 = 0.f, acc1 = 0.f, l = 0.f;
    int e = r0;
    for (; e + 8 <= r1; e += 8) {
        #pragma unroll
        for (int j = 0; j < 8; j++) {
            int s = g_csr[e + j];                  // warp-broadcast
            float lg = g_s[s] + dn;                // warp-broadcast gather
            lg = lg > 0.f ? lg : 0.2f * lg;        // LeakyReLU(0.2)
            float w = __expf(lg);
            float2 v = __half22float2(h2[s * 32 + lane]);
            l += w;
            acc0 += w * v.x;
            acc1 += w * v.y;
        }
    }
    for (; e < r1; e++) {
        int s = g_csr[e];
        float lg = g_s[s] + dn;
        lg = lg > 0.f ? lg : 0.2f * lg;
        float w = __expf(lg);
        float2 v = __half22float2(h2[s * 32 + lane]);
        l += w;
        acc0 += w * v.x;
        acc1 += w * v.y;
    }
    float inv = 1.f / l;
    float2 b = bias2[lane];
    out2[node * 32 + lane] = __floats2half2_rn(
        fmaxf(acc0 * inv + b.x, 0.f),              // ReLU
        fmaxf(acc1 * inv + b.y, 0.f));
}

// ---------------- last layer projection (64 -> 1) ----------------
__global__ void k_lastproj(const __half2* __restrict__ h2, const float* __restrict__ WL,
                           const float* __restrict__ asL, const float* __restrict__ adL) {
    int gtid = blockIdx.x * blockDim.x + threadIdx.x;
    int node = gtid >> 5, lane = gtid & 31;
    if (node >= N_NODES) return;
    float2 f = __half22float2(h2[node * 32 + lane]);
    float2 w = ((const float2*)WL)[lane];
    float p = f.x * w.x + f.y * w.y;
    #pragma unroll
    for (int o = 16; o > 0; o >>= 1) p += __shfl_xor_sync(0xffffffffu, p, o);
    if (lane == 0) {
        g_pL[node] = make_float2(p, p * asL[0]);   // (hL, sL) packed
        g_dL[node] = p * adL[0];
    }
}

// ---------------- 1-wide attention aggregation + sigmoid (single pass) ----------------
__global__ void k_agg1(const float* __restrict__ bL, float* __restrict__ out) {
    int gtid = blockIdx.x * blockDim.x + threadIdx.x;
    int node = gtid >> 5, lane = gtid & 31;
    if (node >= N_NODES) return;
    int r0 = g_rowptr[node], r1 = g_rowptr[node + 1];
    float dn = g_dL[node];
    float l = 0.f, acc = 0.f;
    for (int e = r0 + lane; e < r1; e += 32) {
        float2 p = g_pL[g_csr[e]];                 // one 32B sector: (hL, sL)
        float lg = p.y + dn;
        lg = lg > 0.f ? lg : 0.2f * lg;
        float w = __expf(lg);
        l += w;
        acc += w * p.x;
    }
    #pragma unroll
    for (int o = 16; o > 0; o >>= 1) {
        l   += __shfl_xor_sync(0xffffffffu, l, o);
        acc += __shfl_xor_sync(0xffffffffu, acc, o);
    }
    if (lane == 0) {
        float z = acc / l + bL[0];
        out[node] = 1.f / (1.f + __expf(-z));
    }
}

// ---------------- launch ----------------
extern "C" void kernel_launch(void* const* d_in, const int* in_sizes, int n_in,
                              void* d_out, int out_size) {
    const float* x    = (const float*)d_in[0];
    const int*   ei   = (const int*)d_in[1];   // int32
    // d_in[2] = edge_weight (ignored: edge_dim=None)
    const float* W0   = (const float*)d_in[3];
    const float* as0  = (const float*)d_in[4];
    const float* ad0  = (const float*)d_in[5];
    const float* b0   = (const float*)d_in[6];
    const float* Wm   = (const float*)d_in[7];
    const float* asm_ = (const float*)d_in[8];
    const float* adm  = (const float*)d_in[9];
    const float* bm   = (const float*)d_in[10];
    const float* WL   = (const float*)d_in[11];
    const float* asL  = (const float*)d_in[12];
    const float* adL  = (const float*)d_in[13];
    const float* bL   = (const float*)d_in[14];
    float* out = (float*)d_out;

    __half *bufA, *bufB;
    cudaGetSymbolAddress((void**)&bufA, g_bufA);
    cudaGetSymbolAddress((void**)&bufB, g_bufB);

    const int TB = 256;
    // CSR build (by dst, self-loops appended)
    k_zero_cnt<<<(N_NODES + TB - 1) / TB, TB>>>();
    k_hist<<<(E_TOT + TB - 1) / TB, TB>>>(ei);
    k_scan<<<1, 1024>>>();
    k_scatter<<<(E_TOT + TB - 1) / TB, TB>>>(ei);

    const int aggBlocks = (N_NODES * 32 + TB - 1) / TB;

    // layer 0
    k_layer0<<<(N_NODES * HID + TB - 1) / TB, TB>>>(x, W0, as0, ad0);
    k_agg64<<<aggBlocks, TB>>>((const __half2*)bufB, (const float2*)b0, (__half2*)bufA);

    // middle layers 1..3
    for (int i = 0; i < 3; i++) {
        k_gemm64<<<(N_NODES + 63) / 64, 256>>>((const __half2*)bufA, Wm + i * HID * HID,
                                               asm_ + i * HID, adm + i * HID,
                                               (__half2*)bufB);
        k_agg64<<<aggBlocks, TB>>>((const __half2*)bufB, (const float2*)(bm + i * HID),
                                   (__half2*)bufA);
    }

    // last layer (64 -> 1) + sigmoid
    k_lastproj<<<aggBlocks, TB>>>((const __half2*)bufA, WL, asL, adL);
    k_agg1<<<aggBlocks, TB>>>(bL, out);
}

// round 5
// speedup vs baseline: 1.0797x; 1.0797x over previous
#include <cuda_runtime.h>
#include <cuda_fp16.h>

#define N_NODES 100000
#define N_EDGES 6400000
#define E_TOT   (N_EDGES + N_NODES)
#define HID 64

// ---------------- scratch (static device globals; no allocation) ----------------
__device__ __half g_bufA[N_NODES * HID];  // ping  (packed: half2 at n*32+l = feats 2l,2l+1)
__device__ __half g_bufB[N_NODES * HID];  // pong
__device__ float g_s[N_NODES];            // h @ a_s (fp32)
__device__ float g_d[N_NODES];            // h @ a_d (fp32)
__device__ int   g_csr[E_TOT];            // src ids, grouped by dst
__device__ int   g_dst[E_TOT];            // dst id per CSR slot
__device__ float g_w[E_TOT];              // per-edge softmax weight (unnormalized)
__device__ int   g_rowptr[N_NODES + 1];
__device__ int   g_cnt[N_NODES];          // static zero-init; re-zeroed by k_scan
__device__ int   g_cursor[N_NODES];
__device__ float2 g_pL[N_NODES];          // last layer: (hL, sL) packed
__device__ float g_dL[N_NODES];

// ---------------- CSR build ----------------
// edge_index is int32 on device (JAX x64 disabled)
__global__ void k_hist(const int* __restrict__ ei) {
    int i = blockIdx.x * blockDim.x + threadIdx.x;
    if (i >= E_TOT) return;
    int dst = (i < N_EDGES) ? ei[N_EDGES + i] : (i - N_EDGES);  // self-loops appended
    atomicAdd(&g_cnt[dst], 1);
}

// single-block exclusive scan over 100k counts -> rowptr (+ cursor copy); zeroes g_cnt
__global__ void k_scan() {
    __shared__ int sh[32];
    int tid = threadIdx.x, lane = tid & 31, wid = tid >> 5;
    int carry = 0;
    if (tid == 0) g_rowptr[0] = 0;
    for (int base = 0; base < N_NODES; base += 1024) {
        int i = base + tid;
        int v = (i < N_NODES) ? g_cnt[i] : 0;
        if (i < N_NODES) g_cnt[i] = 0;           // reset for next graph replay
        int x = v;
        #pragma unroll
        for (int o = 1; o < 32; o <<= 1) {
            int y = __shfl_up_sync(0xffffffffu, x, o);
            if (lane >= o) x += y;
        }
        if (lane == 31) sh[wid] = x;
        __syncthreads();
        if (wid == 0) {
            int y = sh[lane];
            #pragma unroll
            for (int o = 1; o < 32; o <<= 1) {
                int z = __shfl_up_sync(0xffffffffu, y, o);
                if (lane >= o) y += z;
            }
            sh[lane] = y;
        }
        __syncthreads();
        int off = (wid > 0) ? sh[wid - 1] : 0;
        int incl = x + off + carry;
        if (i < N_NODES) { g_rowptr[i + 1] = incl; g_cursor[i] = incl - v; }
        carry += sh[31];
        __syncthreads();
    }
}

__global__ void k_scatter(const int* __restrict__ ei) {
    int i = blockIdx.x * blockDim.x + threadIdx.x;
    if (i >= E_TOT) return;
    int src, dst;
    if (i < N_EDGES) { src = ei[i]; dst = ei[N_EDGES + i]; }
    else             { src = i - N_EDGES; dst = src; }
    int pos = atomicAdd(&g_cursor[dst], 1);
    g_csr[pos] = src;
    g_dst[pos] = dst;
}

// ---------------- per-edge weight: w = exp(leakyrelu(s[src] + d[dst])) ----------------
// Coalesced csr/dst reads; g_d[dst] is segment-constant (L1 broadcast); g_s random gather
// with huge MLP. Single-pass softmax is valid by shift-invariance (logits O(1)).
__global__ void k_edgew() {
    int e = blockIdx.x * blockDim.x + threadIdx.x;
    if (e >= E_TOT) return;
    float lg = g_s[g_csr[e]] + g_d[g_dst[e]];
    lg = lg > 0.f ? lg : 0.2f * lg;              // LeakyReLU(0.2)
    g_w[e] = __expf(lg);
}

// ---------------- layer 0: h = x (Nx1) * W0 (1x64); s,d scalars ----------------
__global__ void k_layer0(const float* __restrict__ x, const float* __restrict__ W0,
                         const float* __restrict__ as0, const float* __restrict__ ad0) {
    int idx = blockIdx.x * blockDim.x + threadIdx.x;
    if (idx >= N_NODES * HID) return;
    int n = idx >> 6, c = idx & 63;
    float xv = x[n];
    g_bufB[idx] = __float2half(xv * W0[c]);
    if (c == 0) {
        float c1 = 0.f, c2 = 0.f;
        #pragma unroll
        for (int k = 0; k < HID; k++) { c1 += W0[k] * as0[k]; c2 += W0[k] * ad0[k]; }
        g_s[n] = xv * c1;
        g_d[n] = xv * c2;
    }
}

// ---------------- 64x64 GEMM + attention projections (warp per node) ----------------
// Packed layout: half2 at row*32+lane holds features (2l, 2l+1).
__global__ void __launch_bounds__(256)
k_gemm64(const __half2* __restrict__ hin2, const float* __restrict__ W,
         const float* __restrict__ a_s, const float* __restrict__ a_d,
         __half2* __restrict__ hout2) {
    __shared__ float Wsm[HID * HID];
    int tid = threadIdx.x;
    for (int i = tid; i < HID * HID; i += 256) Wsm[i] = W[i];
    __syncthreads();
    const float2* W2 = (const float2*)Wsm;   // row k: W2[k*32+l] = (W[k,2l], W[k,2l+1])
    int lane = tid & 31, warp = tid >> 5;
    float2 as2 = ((const float2*)a_s)[lane];
    float2 ad2 = ((const float2*)a_d)[lane];
    int nbase = blockIdx.x * 64 + warp * 8;
    for (int j = 0; j < 8; j++) {
        int n = nbase + j;
        if (n >= N_NODES) return;
        float2 f = __half22float2(hin2[n * 32 + lane]);
        float accx = 0.f, accy = 0.f;
        #pragma unroll
        for (int kk = 0; kk < 32; kk++) {
            float bx = __shfl_sync(0xffffffffu, f.x, kk);
            float by = __shfl_sync(0xffffffffu, f.y, kk);
            float2 w0 = W2[(2 * kk) * 32 + lane];
            float2 w1 = W2[(2 * kk + 1) * 32 + lane];
            accx += bx * w0.x + by * w1.x;
            accy += bx * w0.y + by * w1.y;
        }
        hout2[n * 32 + lane] = __floats2half2_rn(accx, accy);
        float ps = accx * as2.x + accy * as2.y;
        float pd = accx * ad2.x + accy * ad2.y;
        #pragma unroll
        for (int o = 16; o > 0; o >>= 1) {
            ps += __shfl_down_sync(0xffffffffu, ps, o);
            pd += __shfl_down_sync(0xffffffffu, pd, o);
        }
        if (lane == 0) { g_s[n] = ps; g_d[n] = pd; }
    }
}

// ---------------- 64-wide attention aggregation: warp per dst node ----------------
// csr + precomputed w are loaded coalesced (one lane-strided load per 32 edges),
// broadcast via shfl. Hot loop per edge: 2 SHFL + 1 coalesced 128B gather + FMAs.
__global__ void __launch_bounds__(256)
k_agg64(const __half2* __restrict__ h2, const float2* __restrict__ bias2,
        __half2* __restrict__ out2) {
    int gtid = blockIdx.x * blockDim.x + threadIdx.x;
    int node = gtid >> 5, lane = gtid & 31;
    if (node >= N_NODES) return;
    int r0 = g_rowptr[node], r1 = g_rowptr[node + 1];

    float acc0 = 0.f, acc1 = 0.f, l = 0.f;
    int base = r0;
    for (; base + 32 <= r1; base += 32) {
        int   sl = g_csr[base + lane];             // coalesced
        float wl = g_w[base + lane];               // coalesced
        #pragma unroll
        for (int j = 0; j < 32; j++) {
            int   s = __shfl_sync(0xffffffffu, sl, j);
            float w = __shfl_sync(0xffffffffu, wl, j);
            float2 v = __half22float2(h2[s * 32 + lane]);
            l += w;
            acc0 += w * v.x;
            acc1 += w * v.y;
        }
    }
    int rem = r1 - base;
    if (rem > 0) {
        int   sl = (lane < rem) ? g_csr[base + lane] : 0;
        float wl = (lane < rem) ? g_w[base + lane] : 0.f;
        for (int j = 0; j < rem; j++) {
            int   s = __shfl_sync(0xffffffffu, sl, j);
            float w = __shfl_sync(0xffffffffu, wl, j);
            float2 v = __half22float2(h2[s * 32 + lane]);
            l += w;
            acc0 += w * v.x;
            acc1 += w * v.y;
        }
    }
    float inv = 1.f / l;
    float2 b = bias2[lane];
    out2[node * 32 + lane] = __floats2half2_rn(
        fmaxf(acc0 * inv + b.x, 0.f),              // ReLU
        fmaxf(acc1 * inv + b.y, 0.f));
}

// ---------------- last layer projection (64 -> 1) ----------------
__global__ void k_lastproj(const __half2* __restrict__ h2, const float* __restrict__ WL,
                           const float* __restrict__ asL, const float* __restrict__ adL) {
    int gtid = blockIdx.x * blockDim.x + threadIdx.x;
    int node = gtid >> 5, lane = gtid & 31;
    if (node >= N_NODES) return;
    float2 f = __half22float2(h2[node * 32 + lane]);
    float2 w = ((const float2*)WL)[lane];
    float p = f.x * w.x + f.y * w.y;
    #pragma unroll
    for (int o = 16; o > 0; o >>= 1) p += __shfl_xor_sync(0xffffffffu, p, o);
    if (lane == 0) {
        g_pL[node] = make_float2(p, p * asL[0]);   // (hL, sL) packed
        g_dL[node] = p * adL[0];
    }
}

// ---------------- 1-wide attention aggregation + sigmoid (single pass) ----------------
__global__ void k_agg1(const float* __restrict__ bL, float* __restrict__ out) {
    int gtid = blockIdx.x * blockDim.x + threadIdx.x;
    int node = gtid >> 5, lane = gtid & 31;
    if (node >= N_NODES) return;
    int r0 = g_rowptr[node], r1 = g_rowptr[node + 1];
    float dn = g_dL[node];
    float l = 0.f, acc = 0.f;
    for (int e = r0 + lane; e < r1; e += 32) {
        float2 p = g_pL[g_csr[e]];                 // one 32B sector: (hL, sL)
        float lg = p.y + dn;
        lg = lg > 0.f ? lg : 0.2f * lg;
        float w = __expf(lg);
        l += w;
        acc += w * p.x;
    }
    #pragma unroll
    for (int o = 16; o > 0; o >>= 1) {
        l   += __shfl_xor_sync(0xffffffffu, l, o);
        acc += __shfl_xor_sync(0xffffffffu, acc, o);
    }
    if (lane == 0) {
        float z = acc / l + bL[0];
        out[node] = 1.f / (1.f + __expf(-z));
    }
}

// ---------------- launch ----------------
extern "C" void kernel_launch(void* const* d_in, const int* in_sizes, int n_in,
                              void* d_out, int out_size) {
    const float* x    = (const float*)d_in[0];
    const int*   ei   = (const int*)d_in[1];   // int32
    // d_in[2] = edge_weight (ignored: edge_dim=None)
    const float* W0   = (const float*)d_in[3];
    const float* as0  = (const float*)d_in[4];
    const float* ad0  = (const float*)d_in[5];
    const float* b0   = (const float*)d_in[6];
    const float* Wm   = (const float*)d_in[7];
    const float* asm_ = (const float*)d_in[8];
    const float* adm  = (const float*)d_in[9];
    const float* bm   = (const float*)d_in[10];
    const float* WL   = (const float*)d_in[11];
    const float* asL  = (const float*)d_in[12];
    const float* adL  = (const float*)d_in[13];
    const float* bL   = (const float*)d_in[14];
    float* out = (float*)d_out;

    __half *bufA, *bufB;
    cudaGetSymbolAddress((void**)&bufA, g_bufA);
    cudaGetSymbolAddress((void**)&bufB, g_bufB);

    const int TB = 256;
    const int aggBlocks  = (N_NODES * 32 + TB - 1) / TB;
    const int edgeBlocks = (E_TOT + TB - 1) / TB;

    // (1) layer 0 projection first (independent of CSR) — keeps agg64 at ncu slot 6
    k_layer0<<<(N_NODES * HID + TB - 1) / TB, TB>>>(x, W0, as0, ad0);
    // (2-4) CSR build (by dst, self-loops appended); g_cnt zeroed by static init / k_scan
    k_hist<<<edgeBlocks, TB>>>(ei);
    k_scan<<<1, 1024>>>();
    k_scatter<<<edgeBlocks, TB>>>(ei);

    // (5-6) layer 0 attention
    k_edgew<<<edgeBlocks, TB>>>();
    k_agg64<<<aggBlocks, TB>>>((const __half2*)bufB, (const float2*)b0, (__half2*)bufA);

    // middle layers 1..3
    for (int i = 0; i < 3; i++) {
        k_gemm64<<<(N_NODES + 63) / 64, 256>>>((const __half2*)bufA, Wm + i * HID * HID,
                                               asm_ + i * HID, adm + i * HID,
                                               (__half2*)bufB);
        k_edgew<<<edgeBlocks, TB>>>();
        k_agg64<<<aggBlocks, TB>>>((const __half2*)bufB, (const float2*)(bm + i * HID),
                                   (__half2*)bufA);
    }

    // last layer (64 -> 1) + sigmoid
    k_lastproj<<<aggBlocks, TB>>>((const __half2*)bufA, WL, asL, adL);
    k_agg1<<<aggBlocks, TB>>>(bL, out);
}

// round 6
// speedup vs baseline: 1.2245x; 1.1341x over previous
#include <cuda_runtime.h>
#include <cuda_fp16.h>

#define N_NODES 100000
#define N_EDGES 6400000
#define E_TOT   (N_EDGES + N_NODES)
#define HID 64

// ---------------- scratch (static device globals; no allocation) ----------------
__device__ __half g_bufA[N_NODES * HID];  // ping  (packed: half2 at n*32+l = feats 2l,2l+1)
__device__ __half g_bufB[N_NODES * HID];  // pong
__device__ float g_s[N_NODES];            // h @ a_s (fp32)
__device__ float g_d[N_NODES];            // h @ a_d (fp32)
__device__ int   g_csr[E_TOT];            // src ids, grouped by dst
__device__ int   g_rowptr[N_NODES + 1];
__device__ int   g_cnt[N_NODES];          // static zero-init; re-zeroed by k_scan
__device__ int   g_cursor[N_NODES];
__device__ float2 g_pL[N_NODES];          // last layer: (hL, sL) packed
__device__ float g_dL[N_NODES];

// ---------------- CSR build ----------------
// edge_index is int32 on device (JAX x64 disabled)
__global__ void k_hist(const int* __restrict__ ei) {
    int i = blockIdx.x * blockDim.x + threadIdx.x;
    if (i >= E_TOT) return;
    int dst = (i < N_EDGES) ? ei[N_EDGES + i] : (i - N_EDGES);  // self-loops appended
    atomicAdd(&g_cnt[dst], 1);
}

// single-block exclusive scan over 100k counts -> rowptr (+ cursor copy); zeroes g_cnt
__global__ void k_scan() {
    __shared__ int sh[32];
    int tid = threadIdx.x, lane = tid & 31, wid = tid >> 5;
    int carry = 0;
    if (tid == 0) g_rowptr[0] = 0;
    for (int base = 0; base < N_NODES; base += 1024) {
        int i = base + tid;
        int v = (i < N_NODES) ? g_cnt[i] : 0;
        if (i < N_NODES) g_cnt[i] = 0;           // reset for next graph replay
        int x = v;
        #pragma unroll
        for (int o = 1; o < 32; o <<= 1) {
            int y = __shfl_up_sync(0xffffffffu, x, o);
            if (lane >= o) x += y;
        }
        if (lane == 31) sh[wid] = x;
        __syncthreads();
        if (wid == 0) {
            int y = sh[lane];
            #pragma unroll
            for (int o = 1; o < 32; o <<= 1) {
                int z = __shfl_up_sync(0xffffffffu, y, o);
                if (lane >= o) y += z;
            }
            sh[lane] = y;
        }
        __syncthreads();
        int off = (wid > 0) ? sh[wid - 1] : 0;
        int incl = x + off + carry;
        if (i < N_NODES) { g_rowptr[i + 1] = incl; g_cursor[i] = incl - v; }
        carry += sh[31];
        __syncthreads();
    }
}

__global__ void k_scatter(const int* __restrict__ ei) {
    int i = blockIdx.x * blockDim.x + threadIdx.x;
    if (i >= E_TOT) return;
    int src, dst;
    if (i < N_EDGES) { src = ei[i]; dst = ei[N_EDGES + i]; }
    else             { src = i - N_EDGES; dst = src; }
    int pos = atomicAdd(&g_cursor[dst], 1);
    g_csr[pos] = src;
}

// ---------------- layer 0: h = x (Nx1) * W0 (1x64); s,d scalars ----------------
__global__ void k_layer0(const float* __restrict__ x, const float* __restrict__ W0,
                         const float* __restrict__ as0, const float* __restrict__ ad0) {
    int idx = blockIdx.x * blockDim.x + threadIdx.x;
    if (idx >= N_NODES * HID) return;
    int n = idx >> 6, c = idx & 63;
    float xv = x[n];
    g_bufB[idx] = __float2half(xv * W0[c]);
    if (c == 0) {
        float c1 = 0.f, c2 = 0.f;
        #pragma unroll
        for (int k = 0; k < HID; k++) { c1 += W0[k] * as0[k]; c2 += W0[k] * ad0[k]; }
        g_s[n] = xv * c1;
        g_d[n] = xv * c2;
    }
}

// ---------------- 64x64 GEMM + attention projections (warp per node) ----------------
// Packed layout: half2 at row*32+lane holds features (2l, 2l+1).
__global__ void __launch_bounds__(256)
k_gemm64(const __half2* __restrict__ hin2, const float* __restrict__ W,
         const float* __restrict__ a_s, const float* __restrict__ a_d,
         __half2* __restrict__ hout2) {
    __shared__ float Wsm[HID * HID];
    int tid = threadIdx.x;
    for (int i = tid; i < HID * HID; i += 256) Wsm[i] = W[i];
    __syncthreads();
    const float2* W2 = (const float2*)Wsm;   // row k: W2[k*32+l] = (W[k,2l], W[k,2l+1])
    int lane = tid & 31, warp = tid >> 5;
    float2 as2 = ((const float2*)a_s)[lane];
    float2 ad2 = ((const float2*)a_d)[lane];
    int nbase = blockIdx.x * 64 + warp * 8;
    for (int j = 0; j < 8; j++) {
        int n = nbase + j;
        if (n >= N_NODES) return;
        float2 f = __half22float2(hin2[n * 32 + lane]);
        float accx = 0.f, accy = 0.f;
        #pragma unroll
        for (int kk = 0; kk < 32; kk++) {
            float bx = __shfl_sync(0xffffffffu, f.x, kk);
            float by = __shfl_sync(0xffffffffu, f.y, kk);
            float2 w0 = W2[(2 * kk) * 32 + lane];
            float2 w1 = W2[(2 * kk + 1) * 32 + lane];
            accx += bx * w0.x + by * w1.x;
            accy += bx * w0.y + by * w1.y;
        }
        hout2[n * 32 + lane] = __floats2half2_rn(accx, accy);
        float ps = accx * as2.x + accy * as2.y;
        float pd = accx * ad2.x + accy * ad2.y;
        #pragma unroll
        for (int o = 16; o > 0; o >>= 1) {
            ps += __shfl_down_sync(0xffffffffu, ps, o);
            pd += __shfl_down_sync(0xffffffffu, pd, o);
        }
        if (lane == 0) { g_s[n] = ps; g_d[n] = pd; }
    }
}

// ---------------- 64-wide attention aggregation: warp per dst node ----------------
// Fused weights: per 32-edge chunk each lane loads csr (coalesced), gathers g_s
// lane-parallel (full MLP, L2-resident), computes w = exp(leakyrelu(s+dn)) in
// register, then (s, w) are shfl-broadcast. Single-pass softmax (shift-invariant;
// logits O(1), exp cannot overflow). Hot loop per edge: 2 SHFL + 1 coalesced
// 128B row gather + FMAs.
__global__ void __launch_bounds__(256)
k_agg64(const __half2* __restrict__ h2, const float2* __restrict__ bias2,
        __half2* __restrict__ out2) {
    int gtid = blockIdx.x * blockDim.x + threadIdx.x;
    int node = gtid >> 5, lane = gtid & 31;
    if (node >= N_NODES) return;
    int r0 = g_rowptr[node], r1 = g_rowptr[node + 1];
    float dn = g_d[node];

    float acc0 = 0.f, acc1 = 0.f, l = 0.f;
    int base = r0;
    for (; base + 32 <= r1; base += 32) {
        int   sl = g_csr[base + lane];             // coalesced
        float lg = g_s[sl] + dn;                   // lane-parallel gather
        lg = lg > 0.f ? lg : 0.2f * lg;            // LeakyReLU(0.2)
        float wl = __expf(lg);
        #pragma unroll
        for (int j = 0; j < 32; j++) {
            int   s = __shfl_sync(0xffffffffu, sl, j);
            float w = __shfl_sync(0xffffffffu, wl, j);
            float2 v = __half22float2(h2[s * 32 + lane]);
            l += w;
            acc0 += w * v.x;
            acc1 += w * v.y;
        }
    }
    int rem = r1 - base;
    if (rem > 0) {
        int   sl = (lane < rem) ? g_csr[base + lane] : 0;
        float wl = 0.f;
        if (lane < rem) {
            float lg = g_s[sl] + dn;
            lg = lg > 0.f ? lg : 0.2f * lg;
            wl = __expf(lg);
        }
        for (int j = 0; j < rem; j++) {
            int   s = __shfl_sync(0xffffffffu, sl, j);
            float w = __shfl_sync(0xffffffffu, wl, j);
            float2 v = __half22float2(h2[s * 32 + lane]);
            l += w;
            acc0 += w * v.x;
            acc1 += w * v.y;
        }
    }
    float inv = 1.f / l;
    float2 b = bias2[lane];
    out2[node * 32 + lane] = __floats2half2_rn(
        fmaxf(acc0 * inv + b.x, 0.f),              // ReLU
        fmaxf(acc1 * inv + b.y, 0.f));
}

// ---------------- last layer projection (64 -> 1) ----------------
__global__ void k_lastproj(const __half2* __restrict__ h2, const float* __restrict__ WL,
                           const float* __restrict__ asL, const float* __restrict__ adL) {
    int gtid = blockIdx.x * blockDim.x + threadIdx.x;
    int node = gtid >> 5, lane = gtid & 31;
    if (node >= N_NODES) return;
    float2 f = __half22float2(h2[node * 32 + lane]);
    float2 w = ((const float2*)WL)[lane];
    float p = f.x * w.x + f.y * w.y;
    #pragma unroll
    for (int o = 16; o > 0; o >>= 1) p += __shfl_xor_sync(0xffffffffu, p, o);
    if (lane == 0) {
        g_pL[node] = make_float2(p, p * asL[0]);   // (hL, sL) packed
        g_dL[node] = p * adL[0];
    }
}

// ---------------- 1-wide attention aggregation + sigmoid (single pass) ----------------
__global__ void k_agg1(const float* __restrict__ bL, float* __restrict__ out) {
    int gtid = blockIdx.x * blockDim.x + threadIdx.x;
    int node = gtid >> 5, lane = gtid & 31;
    if (node >= N_NODES) return;
    int r0 = g_rowptr[node], r1 = g_rowptr[node + 1];
    float dn = g_dL[node];
    float l = 0.f, acc = 0.f;
    for (int e = r0 + lane; e < r1; e += 32) {
        float2 p = g_pL[g_csr[e]];                 // one 32B sector: (hL, sL)
        float lg = p.y + dn;
        lg = lg > 0.f ? lg : 0.2f * lg;
        float w = __expf(lg);
        l += w;
        acc += w * p.x;
    }
    #pragma unroll
    for (int o = 16; o > 0; o >>= 1) {
        l   += __shfl_xor_sync(0xffffffffu, l, o);
        acc += __shfl_xor_sync(0xffffffffu, acc, o);
    }
    if (lane == 0) {
        float z = acc / l + bL[0];
        out[node] = 1.f / (1.f + __expf(-z));
    }
}

// ---------------- launch ----------------
extern "C" void kernel_launch(void* const* d_in, const int* in_sizes, int n_in,
                              void* d_out, int out_size) {
    const float* x    = (const float*)d_in[0];
    const int*   ei   = (const int*)d_in[1];   // int32
    // d_in[2] = edge_weight (ignored: edge_dim=None)
    const float* W0   = (const float*)d_in[3];
    const float* as0  = (const float*)d_in[4];
    const float* ad0  = (const float*)d_in[5];
    const float* b0   = (const float*)d_in[6];
    const float* Wm   = (const float*)d_in[7];
    const float* asm_ = (const float*)d_in[8];
    const float* adm  = (const float*)d_in[9];
    const float* bm   = (const float*)d_in[10];
    const float* WL   = (const float*)d_in[11];
    const float* asL  = (const float*)d_in[12];
    const float* adL  = (const float*)d_in[13];
    const float* bL   = (const float*)d_in[14];
    float* out = (float*)d_out;

    __half *bufA, *bufB;
    cudaGetSymbolAddress((void**)&bufA, g_bufA);
    cudaGetSymbolAddress((void**)&bufB, g_bufB);

    const int TB = 256;
    const int aggBlocks  = (N_NODES * 32 + TB - 1) / TB;
    const int edgeBlocks = (E_TOT + TB - 1) / TB;

    // layer 0 projection first (independent of CSR); then CSR build
    k_layer0<<<(N_NODES * HID + TB - 1) / TB, TB>>>(x, W0, as0, ad0);
    k_hist<<<edgeBlocks, TB>>>(ei);
    k_scan<<<1, 1024>>>();
    k_scatter<<<edgeBlocks, TB>>>(ei);

    // layer 0 attention (slot 5 for ncu -s 5 -c 1)
    k_agg64<<<aggBlocks, TB>>>((const __half2*)bufB, (const float2*)b0, (__half2*)bufA);

    // middle layers 1..3
    for (int i = 0; i < 3; i++) {
        k_gemm64<<<(N_NODES + 63) / 64, 256>>>((const __half2*)bufA, Wm + i * HID * HID,
                                               asm_ + i * HID, adm + i * HID,
                                               (__half2*)bufB);
        k_agg64<<<aggBlocks, TB>>>((const __half2*)bufB, (const float2*)(bm + i * HID),
                                   (__half2*)bufA);
    }

    // last layer (64 -> 1) + sigmoid
    k_lastproj<<<aggBlocks, TB>>>((const __half2*)bufA, WL, asL, adL);
    k_agg1<<<aggBlocks, TB>>>(bL, out);
}